// round 14
// baseline (speedup 1.0000x reference)
#include <cuda_runtime.h>
#include <cstdint>

#define BATCH 512
#define CHANNELS 256
#define KXS 6
#define KZ 22
#define HO 17
#define OUT_PER_B 289
#define N_OUT (BATCH*OUT_PER_B)

#define SPLITS 16
#define CH_PER_SPLIT 16             // one chunk per CTA
#define PAIRS_C 8
#define THREADS 144                 // 8 pairs x (9 row-groups x 2 col-halves)

#define ZPAIR_FLOATS (KZ*KZ*2)      // 968
#define ZROW_PAIRF 44
#define XPAIR_FLOATS (KXS*KXS*2)    // 72
#define ZBUF_FLOATS (PAIRS_C*ZPAIR_FLOATS)   // 7744
#define XBUF_FLOATS (PAIRS_C*XPAIR_FLOATS)   // 576
#define SMEM_BYTES ((ZBUF_FLOATS+XBUF_FLOATS)*4)   // 33280

#define Z_UNITS (PAIRS_C*121)       // 968 float4-pair units
#define X_UNITS (PAIRS_C*9)         // 72
#define PFK 7                       // 968 = 6*144 + 104

typedef unsigned long long ull;

__device__ float g_partial[SPLITS * N_OUT];

__device__ __forceinline__ void fma2(ull& d, ull a, ull b) {
    asm("fma.rn.f32x2 %0, %1, %2, %0;" : "+l"(d) : "l"(a), "l"(b));
}
__device__ __forceinline__ void unpack2(ull v, float& lo, float& hi) {
    asm("mov.b64 {%0, %1}, %2;" : "=f"(lo), "=f"(hi) : "l"(v));
}

__global__ __launch_bounds__(THREADS, 4)
void corr_main_kernel(const float* __restrict__ x, const float* __restrict__ z)
{
    extern __shared__ float smem[];
    float* zbuf = smem;
    float* xbuf = smem + ZBUF_FLOATS;

    const int tid = threadIdx.x;
    const int p   = tid / 18;        // pair lane 0..7
    const int r18 = tid - p * 18;
    const int ch  = r18 / 9;         // column half: 0 -> cols 0..8, 1 -> cols 9..16
    const int g   = r18 - ch * 9;    // row group: owns rows 2g, 2g+1

    const int b     = blockIdx.x >> 4;
    const int split = blockIdx.x & 15;
    const int cbase = split * CH_PER_SPLIT;

    // ---- stage the single 16-channel chunk (8 interleaved pairs) ----
    const float4* zg = reinterpret_cast<const float4*>(
        z + ((size_t)b * CHANNELS + cbase) * (KZ * KZ));
    const float4* xg = reinterpret_cast<const float4*>(
        x + ((size_t)b * CHANNELS + cbase) * (KXS * KXS));

    #pragma unroll
    for (int k = 0; k < PFK; k++) {
        int u = tid + k * THREADS;
        if (u < Z_UNITS) {
            int pu = u / 121;
            int w4 = u - pu * 121;
            float4 a = zg[2 * pu * 121 + w4];
            float4 c = zg[2 * pu * 121 + w4 + 121];
            float4* d4 = reinterpret_cast<float4*>(zbuf + pu * ZPAIR_FLOATS + 8 * w4);
            d4[0] = make_float4(a.x, c.x, a.y, c.y);
            d4[1] = make_float4(a.z, c.z, a.w, c.w);
        }
    }
    if (tid < X_UNITS) {
        int pu = tid / 9;
        int w4 = tid - pu * 9;
        float4 a = xg[2 * pu * 9 + w4];
        float4 c = xg[2 * pu * 9 + w4 + 9];
        float4* d4 = reinterpret_cast<float4*>(xbuf + pu * XPAIR_FLOATS + 8 * w4);
        d4[0] = make_float4(a.x, c.x, a.y, c.y);
        d4[1] = make_float4(a.z, c.z, a.w, c.w);
    }
    __syncthreads();

    // ---- compute: rows {2g, 2g+1}, cols ch*9 + (0..8), pair p ----
    ull acc0[9], acc1[9];
    #pragma unroll
    for (int j = 0; j < 9; j++) { acc0[j] = 0ull; acc1[j] = 0ull; }

    // ch=1 starts reading at pair 8 of each row (float offset 16)
    const float* zc = zbuf + p * ZPAIR_FLOATS + ch * 16;
    const float* xc = xbuf + p * XPAIR_FLOATS;
    const bool has1 = (g < 8);       // row 2g+1 exists only for g<8
    const int baser = 2 * g;

    #pragma unroll
    for (int c = 0; c < 7; c++) {
        if (c < 6 || has1) {
            // z row (2g + c): 14 pairs as 7 LDS.128
            ull zr[14];
            const ulonglong2* z2 =
                reinterpret_cast<const ulonglong2*>(zc + (baser + c) * ZROW_PAIRF);
            #pragma unroll
            for (int q = 0; q < 7; q++) {
                ulonglong2 t = z2[q];
                zr[2*q] = t.x; zr[2*q+1] = t.y;
            }

            if (c < 6) {             // own row 2g, ky = c
                ull xx[6];
                const ulonglong2* x2 =
                    reinterpret_cast<const ulonglong2*>(xc + c * 12);
                ulonglong2 t0 = x2[0], t1 = x2[1], t2 = x2[2];
                xx[0]=t0.x; xx[1]=t0.y; xx[2]=t1.x; xx[3]=t1.y; xx[4]=t2.x; xx[5]=t2.y;
                #pragma unroll
                for (int kx = 0; kx < KXS; kx++)
                    #pragma unroll
                    for (int jj = 0; jj < 8; jj++)
                        fma2(acc0[jj], zr[jj + kx + ch], xx[kx]);
                if (ch == 0) {
                    #pragma unroll
                    for (int kx = 0; kx < KXS; kx++)
                        fma2(acc0[8], zr[8 + kx], xx[kx]);
                }
            }
            if (c >= 1 && has1) {    // own row 2g+1, ky = c-1
                ull xx[6];
                const ulonglong2* x2 =
                    reinterpret_cast<const ulonglong2*>(xc + (c - 1) * 12);
                ulonglong2 t0 = x2[0], t1 = x2[1], t2 = x2[2];
                xx[0]=t0.x; xx[1]=t0.y; xx[2]=t1.x; xx[3]=t1.y; xx[4]=t2.x; xx[5]=t2.y;
                #pragma unroll
                for (int kx = 0; kx < KXS; kx++)
                    #pragma unroll
                    for (int jj = 0; jj < 8; jj++)
                        fma2(acc1[jj], zr[jj + kx + ch], xx[kx]);
                if (ch == 0) {
                    #pragma unroll
                    for (int kx = 0; kx < KXS; kx++)
                        fma2(acc1[8], zr[8 + kx], xx[kx]);
                }
            }
        }
    }

    // ---- fold pair lanes, reduce 8 pairs via smem scratch ----
    __syncthreads();                 // done reading zbuf; reuse as scratch
    float* scratch = smem;           // 8 * 289 floats
    #pragma unroll
    for (int jj = 0; jj < 9; jj++) {
        if (ch == 0 || jj < 8) {
            int col = ch * 9 + jj;
            float lo, hi;
            unpack2(acc0[jj], lo, hi);
            scratch[p * OUT_PER_B + baser * HO + col] = lo + hi;
            if (has1) {
                unpack2(acc1[jj], lo, hi);
                scratch[p * OUT_PER_B + (baser + 1) * HO + col] = lo + hi;
            }
        }
    }
    __syncthreads();

    for (int o = tid; o < OUT_PER_B; o += THREADS) {
        float s = 0.f;
        #pragma unroll
        for (int l = 0; l < PAIRS_C; l++)
            s += scratch[l * OUT_PER_B + o];
        g_partial[(size_t)split * N_OUT + (size_t)b * OUT_PER_B + o] = s;
    }
}

__global__ void corr_reduce_kernel(float* __restrict__ out)
{
    int idx = blockIdx.x * blockDim.x + threadIdx.x;
    if (idx < N_OUT) {
        float s = 0.f;
        #pragma unroll
        for (int sp = 0; sp < SPLITS; sp++)
            s += g_partial[(size_t)sp * N_OUT + idx];
        out[idx] = s;
    }
}

extern "C" void kernel_launch(void* const* d_in, const int* in_sizes, int n_in,
                              void* d_out, int out_size)
{
    const float* a = (const float*)d_in[0];
    const float* bptr = (const float*)d_in[1];
    const float* x;
    const float* z;
    if (in_sizes[0] == BATCH * CHANNELS * KXS * KXS) { x = a;    z = bptr; }
    else                                             { x = bptr; z = a;   }

    float* out = (float*)d_out;

    cudaFuncSetAttribute(corr_main_kernel,
                         cudaFuncAttributeMaxDynamicSharedMemorySize, SMEM_BYTES);
    corr_main_kernel<<<BATCH * SPLITS, THREADS, SMEM_BYTES>>>(x, z);
    corr_reduce_kernel<<<(N_OUT + 255) / 256, 256>>>(out);
}

// round 15
// speedup vs baseline: 2.1372x; 2.1372x over previous
#include <cuda_runtime.h>
#include <cstdint>

#define BATCH 512
#define CHANNELS 256
#define KXS 6
#define KZ 22
#define HO 17
#define OUT_PER_B 289
#define N_OUT (BATCH*OUT_PER_B)

#define SPLITS 8
#define CH_PER_SPLIT (CHANNELS/SPLITS)   // 32
#define CH_CHUNK 8                  // 4 pairs per chunk
#define PAIRS_C 4
#define ITERS (CH_PER_SPLIT/CH_CHUNK)    // 4
#define THREADS 136                 // 17 rows x (4 pairs x 2 ky-halves)
#define LANES 8

#define ZPAIR_FLOATS (KZ*KZ*2)      // 968
#define ZROW_PAIRF 44
#define XPAIR_FLOATS (KXS*KXS*2)    // 72
#define ZBUF_FLOATS (PAIRS_C*ZPAIR_FLOATS)   // 3872
#define XBUF_FLOATS (PAIRS_C*XPAIR_FLOATS)   // 288
#define BUF_FLOATS (ZBUF_FLOATS + XBUF_FLOATS)   // 4160
#define SMEM_BYTES (2*BUF_FLOATS*4)              // 33280

#define Z_UNITS (PAIRS_C*121)       // 484 float4-pair units per chunk
#define X_UNITS (PAIRS_C*9)         // 36
#define PFK 4                       // 484 = 3*136 + 76

#define ZCHUNK_F4 (CH_CHUNK*KZ*KZ/4)    // 968
#define XCHUNK_F4 (CH_CHUNK*KXS*KXS/4)  // 72

typedef unsigned long long ull;

__device__ float g_partial[SPLITS * N_OUT];

__device__ __forceinline__ void fma2(ull& d, ull a, ull b) {
    asm("fma.rn.f32x2 %0, %1, %2, %0;" : "+l"(d) : "l"(a), "l"(b));
}
__device__ __forceinline__ void unpack2(ull v, float& lo, float& hi) {
    asm("mov.b64 {%0, %1}, %2;" : "=f"(lo), "=f"(hi) : "l"(v));
}

__global__ __launch_bounds__(THREADS, 6)
void corr_main_kernel(const float* __restrict__ x, const float* __restrict__ z)
{
    extern __shared__ float smem[];   // ping-pong buffers

    const int tid  = threadIdx.x;
    const int i    = tid % HO;        // output row
    const int lane = tid / HO;        // 0..7
    const int p    = lane >> 1;       // pair 0..3
    const int h    = lane & 1;        // ky half
    const int b     = blockIdx.x >> 3;
    const int split = blockIdx.x & 7;
    const int cbase = split * CH_PER_SPLIT;

    // chunk-invariant staging map (R11 form: one float4-pair unit per slot)
    int zsrc_off[PFK], zdst_off[PFK];
    #pragma unroll
    for (int k = 0; k < PFK; k++) {
        int u = tid + k * THREADS;
        if (u < Z_UNITS) {
            int pu = u / 121;
            int w4 = u - pu * 121;
            zsrc_off[k] = 2 * pu * 121 + w4;
            zdst_off[k] = pu * ZPAIR_FLOATS + 8 * w4;
        } else { zsrc_off[k] = -1; zdst_off[k] = 0; }
    }
    int xsrc_off = -1, xdst_off = 0;
    if (tid < X_UNITS) {
        int pu = tid / 9, w4 = tid - pu * 9;
        xsrc_off = 2 * pu * 9 + w4;
        xdst_off = pu * XPAIR_FLOATS + 8 * w4;
    }

    const float4* zg = reinterpret_cast<const float4*>(
        z + ((size_t)b * CHANNELS + cbase) * (KZ * KZ));
    const float4* xg = reinterpret_cast<const float4*>(
        x + ((size_t)b * CHANNELS + cbase) * (KXS * KXS));

    // ---- stage chunk 0 into buf0 ----
    {
        float* zb0 = smem;
        float* xb0 = smem + ZBUF_FLOATS;
        #pragma unroll
        for (int k = 0; k < PFK; k++)
            if (zsrc_off[k] >= 0) {
                float4 a = zg[zsrc_off[k]];
                float4 c = zg[zsrc_off[k] + 121];
                float4* d4 = reinterpret_cast<float4*>(zb0 + zdst_off[k]);
                d4[0] = make_float4(a.x, c.x, a.y, c.y);
                d4[1] = make_float4(a.z, c.z, a.w, c.w);
            }
        if (xsrc_off >= 0) {
            float4 a = xg[xsrc_off];
            float4 c = xg[xsrc_off + 9];
            float4* d4 = reinterpret_cast<float4*>(xb0 + xdst_off);
            d4[0] = make_float4(a.x, c.x, a.y, c.y);
            d4[1] = make_float4(a.z, c.z, a.w, c.w);
        }
    }
    __syncthreads();

    ull acc[HO];
    #pragma unroll
    for (int j = 0; j < HO; j++) acc[j] = 0ull;

    #pragma unroll 1
    for (int it = 0; it < ITERS; ++it) {
        // ---- stage chunk it+1 into the other buffer ----
        if (it + 1 < ITERS) {
            const float4* zpn = zg + (size_t)(it + 1) * ZCHUNK_F4;
            const float4* xpn = xg + (size_t)(it + 1) * XCHUNK_F4;
            float* zbn = smem + ((it + 1) & 1) * BUF_FLOATS;
            float* xbn = zbn + ZBUF_FLOATS;
            #pragma unroll
            for (int k = 0; k < PFK; k++)
                if (zsrc_off[k] >= 0) {
                    float4 a = zpn[zsrc_off[k]];
                    float4 c = zpn[zsrc_off[k] + 121];
                    float4* d4 = reinterpret_cast<float4*>(zbn + zdst_off[k]);
                    d4[0] = make_float4(a.x, c.x, a.y, c.y);
                    d4[1] = make_float4(a.z, c.z, a.w, c.w);
                }
            if (xsrc_off >= 0) {
                float4 a = xpn[xsrc_off];
                float4 c = xpn[xsrc_off + 9];
                float4* d4 = reinterpret_cast<float4*>(xbn + xdst_off);
                d4[0] = make_float4(a.x, c.x, a.y, c.y);
                d4[1] = make_float4(a.z, c.z, a.w, c.w);
            }
        }

        // ---- compute from buf[it&1] ----
        {
            const float* zbuf = smem + (it & 1) * BUF_FLOATS;
            const float* xbuf = zbuf + ZBUF_FLOATS;
            const float* zc = zbuf + p * ZPAIR_FLOATS;
            const float* xcp = xbuf + p * XPAIR_FLOATS;
            #pragma unroll
            for (int kk = 0; kk < 3; kk++) {
                const int ky = 3 * h + kk;
                const ull* zrow = reinterpret_cast<const ull*>(
                    zc + (i + ky) * ZROW_PAIRF);
                ull xx[6];
                {
                    const ulonglong2* x2 = reinterpret_cast<const ulonglong2*>(
                        xcp + ky * (KXS * 2));
                    ulonglong2 t0 = x2[0], t1 = x2[1], t2 = x2[2];
                    xx[0] = t0.x; xx[1] = t0.y;
                    xx[2] = t1.x; xx[3] = t1.y;
                    xx[4] = t2.x; xx[5] = t2.y;
                }
                ull z13;
                { // half A: positions 0..12 (load 0..13 as 7 LDS.128, carry 13)
                    ull zp[14];
                    const ulonglong2* z2 = reinterpret_cast<const ulonglong2*>(zrow);
                    #pragma unroll
                    for (int q = 0; q < 7; q++) {
                        ulonglong2 t = z2[q];
                        zp[2*q] = t.x; zp[2*q+1] = t.y;
                    }
                    z13 = zp[13];
                    #pragma unroll
                    for (int kx = 0; kx < KXS; kx++)
                        #pragma unroll
                        for (int j = 0; j <= 12 - kx; j++)
                            fma2(acc[j], zp[j + kx], xx[kx]);
                }
                { // half B: positions 13..21 (4 LDS.128, reuse carried 13)
                    ull zq[9];
                    zq[0] = z13;
                    const ulonglong2* z2 = reinterpret_cast<const ulonglong2*>(zrow + 14);
                    #pragma unroll
                    for (int q = 0; q < 4; q++) {
                        ulonglong2 t = z2[q];
                        zq[1+2*q] = t.x; zq[2+2*q] = t.y;
                    }
                    #pragma unroll
                    for (int kx = 0; kx < KXS; kx++)
                        #pragma unroll
                        for (int j = 13 - kx; j < HO; j++)
                            fma2(acc[j], zq[j + kx - 13], xx[kx]);
                }
            }
        }
        __syncthreads();
    }

    // ---- fold pair lanes, reduce 8 lanes via smem scratch ----
    float* scratch = smem;   // 8*289 floats
    #pragma unroll
    for (int j = 0; j < HO; j++) {
        float lo, hi;
        unpack2(acc[j], lo, hi);
        scratch[lane * OUT_PER_B + i * HO + j] = lo + hi;
    }
    __syncthreads();

    for (int o = tid; o < OUT_PER_B; o += THREADS) {
        float s = 0.f;
        #pragma unroll
        for (int l = 0; l < LANES; l++)
            s += scratch[l * OUT_PER_B + o];
        g_partial[((size_t)split * BATCH + b) * OUT_PER_B + o] = s;
    }
}

__global__ void corr_reduce_kernel(float* __restrict__ out)
{
    int idx = blockIdx.x * blockDim.x + threadIdx.x;
    if (idx < N_OUT) {
        float s = 0.f;
        #pragma unroll
        for (int sp = 0; sp < SPLITS; sp++)
            s += g_partial[(size_t)sp * N_OUT + idx];
        out[idx] = s;
    }
}

extern "C" void kernel_launch(void* const* d_in, const int* in_sizes, int n_in,
                              void* d_out, int out_size)
{
    const float* a = (const float*)d_in[0];
    const float* bptr = (const float*)d_in[1];
    const float* x;
    const float* z;
    if (in_sizes[0] == BATCH * CHANNELS * KXS * KXS) { x = a;    z = bptr; }
    else                                             { x = bptr; z = a;   }

    float* out = (float*)d_out;

    cudaFuncSetAttribute(corr_main_kernel,
                         cudaFuncAttributeMaxDynamicSharedMemorySize, SMEM_BYTES);
    corr_main_kernel<<<BATCH * SPLITS, THREADS, SMEM_BYTES>>>(x, z);
    corr_reduce_kernel<<<(N_OUT + 255) / 256, 256>>>(out);
}

// round 16
// speedup vs baseline: 2.3709x; 1.1094x over previous
#include <cuda_runtime.h>
#include <cstdint>

#define BATCH 512
#define CHANNELS 256
#define KXS 6
#define KZ 22
#define HO 17
#define OUT_PER_B 289
#define N_OUT (BATCH*OUT_PER_B)

#define SPLITS 8
#define CH_PER_SPLIT (CHANNELS/SPLITS)   // 32
#define CH_CHUNK 8                  // 4 pairs per chunk
#define PAIRS_C 4
#define ITERS (CH_PER_SPLIT/CH_CHUNK)    // 4
#define THREADS 136                 // 17 rows x (4 pairs x 2 ky-halves)
#define LANES 8

#define ZPAIR_FLOATS (KZ*KZ*2)      // 968
#define ZROW_PAIRF 44
#define XPAIR_FLOATS (KXS*KXS*2)    // 72
#define ZBUF_FLOATS (PAIRS_C*ZPAIR_FLOATS)   // 3872
#define XBUF_FLOATS (PAIRS_C*XPAIR_FLOATS)   // 288
#define BUF_FLOATS (ZBUF_FLOATS + XBUF_FLOATS)   // 4160
#define SMEM_BYTES (2*BUF_FLOATS*4)              // 33280

#define Z_UNITS (PAIRS_C*121)       // 484
#define X_UNITS (PAIRS_C*9)         // 36
#define PFK 4

#define ZCHUNK_F4 (CH_CHUNK*KZ*KZ/4)    // 968
#define XCHUNK_F4 (CH_CHUNK*KXS*KXS/4)  // 72

typedef unsigned long long ull;

__device__ float g_partial[SPLITS * N_OUT];

__device__ __forceinline__ void fma2(ull& d, ull a, ull b) {
    asm("fma.rn.f32x2 %0, %1, %2, %0;" : "+l"(d) : "l"(a), "l"(b));
}
__device__ __forceinline__ void unpack2(ull v, float& lo, float& hi) {
    asm("mov.b64 {%0, %1}, %2;" : "=f"(lo), "=f"(hi) : "l"(v));
}

__global__ __launch_bounds__(THREADS, 5)
void corr_main_kernel(const float* __restrict__ x, const float* __restrict__ z)
{
    extern __shared__ float smem[];   // ping-pong buffers

    const int tid  = threadIdx.x;
    const int i    = tid % HO;        // output row
    const int lane = tid / HO;        // 0..7
    const int p    = lane >> 1;       // pair 0..3
    const int h    = lane & 1;        // ky half
    const int b     = blockIdx.x >> 3;
    const int split = blockIdx.x & 7;
    const int cbase = split * CH_PER_SPLIT;

    // chunk-invariant staging map
    int zsrc_off[PFK], zdst_off[PFK];
    #pragma unroll
    for (int k = 0; k < PFK; k++) {
        int u = tid + k * THREADS;
        if (u < Z_UNITS) {
            int pu = u / 121;
            int w4 = u - pu * 121;
            zsrc_off[k] = 2 * pu * 121 + w4;
            zdst_off[k] = pu * ZPAIR_FLOATS + 8 * w4;
        } else { zsrc_off[k] = -1; zdst_off[k] = 0; }
    }
    int xsrc_off = -1, xdst_off = 0;
    if (tid < X_UNITS) {
        int pu = tid / 9, w4 = tid - pu * 9;
        xsrc_off = 2 * pu * 9 + w4;
        xdst_off = pu * XPAIR_FLOATS + 8 * w4;
    }

    const float4* zg = reinterpret_cast<const float4*>(
        z + ((size_t)b * CHANNELS + cbase) * (KZ * KZ));
    const float4* xg = reinterpret_cast<const float4*>(
        x + ((size_t)b * CHANNELS + cbase) * (KXS * KXS));

    // ---- stage chunk 0 into buf0 (inline LDG->interleave->STS) ----
    {
        float* zb0 = smem;
        float* xb0 = smem + ZBUF_FLOATS;
        #pragma unroll
        for (int k = 0; k < PFK; k++)
            if (zsrc_off[k] >= 0) {
                float4 a = zg[zsrc_off[k]];
                float4 c = zg[zsrc_off[k] + 121];
                float4* d4 = reinterpret_cast<float4*>(zb0 + zdst_off[k]);
                d4[0] = make_float4(a.x, c.x, a.y, c.y);
                d4[1] = make_float4(a.z, c.z, a.w, c.w);
            }
        if (xsrc_off >= 0) {
            float4 a = xg[xsrc_off];
            float4 c = xg[xsrc_off + 9];
            float4* d4 = reinterpret_cast<float4*>(xb0 + xdst_off);
            d4[0] = make_float4(a.x, c.x, a.y, c.y);
            d4[1] = make_float4(a.z, c.z, a.w, c.w);
        }
    }
    __syncthreads();

    ull acc[HO];
    #pragma unroll
    for (int j = 0; j < HO; j++) acc[j] = 0ull;

    #pragma unroll 1
    for (int it = 0; it < ITERS; ++it) {
        // ---- stage chunk it+1 into the other buffer ----
        if (it + 1 < ITERS) {
            const float4* zpn = zg + (size_t)(it + 1) * ZCHUNK_F4;
            const float4* xpn = xg + (size_t)(it + 1) * XCHUNK_F4;
            float* zbn = smem + ((it + 1) & 1) * BUF_FLOATS;
            float* xbn = zbn + ZBUF_FLOATS;
            #pragma unroll
            for (int k = 0; k < PFK; k++)
                if (zsrc_off[k] >= 0) {
                    float4 a = zpn[zsrc_off[k]];
                    float4 c = zpn[zsrc_off[k] + 121];
                    float4* d4 = reinterpret_cast<float4*>(zbn + zdst_off[k]);
                    d4[0] = make_float4(a.x, c.x, a.y, c.y);
                    d4[1] = make_float4(a.z, c.z, a.w, c.w);
                }
            if (xsrc_off >= 0) {
                float4 a = xpn[xsrc_off];
                float4 c = xpn[xsrc_off + 9];
                float4* d4 = reinterpret_cast<float4*>(xbn + xdst_off);
                d4[0] = make_float4(a.x, c.x, a.y, c.y);
                d4[1] = make_float4(a.z, c.z, a.w, c.w);
            }
        }

        // ---- compute from buf[it&1] ----
        {
            const float* zbuf = smem + (it & 1) * BUF_FLOATS;
            const float* xbuf = zbuf + ZBUF_FLOATS;
            const float* zc = zbuf + p * ZPAIR_FLOATS;
            const float* xcp = xbuf + p * XPAIR_FLOATS;
            #pragma unroll
            for (int kk = 0; kk < 3; kk++) {
                const int ky = 3 * h + kk;
                const ull* zrow = reinterpret_cast<const ull*>(
                    zc + (i + ky) * ZROW_PAIRF);
                ull xx[6];
                {
                    const ulonglong2* x2 = reinterpret_cast<const ulonglong2*>(
                        xcp + ky * (KXS * 2));
                    ulonglong2 t0 = x2[0], t1 = x2[1], t2 = x2[2];
                    xx[0] = t0.x; xx[1] = t0.y;
                    xx[2] = t1.x; xx[3] = t1.y;
                    xx[4] = t2.x; xx[5] = t2.y;
                }
                { // half A: positions 0..12
                    ull zp[13];
                    const ulonglong2* z2 = reinterpret_cast<const ulonglong2*>(zrow);
                    #pragma unroll
                    for (int q = 0; q < 6; q++) {
                        ulonglong2 t = z2[q];
                        zp[2*q] = t.x; zp[2*q+1] = t.y;
                    }
                    zp[12] = zrow[12];
                    #pragma unroll
                    for (int kx = 0; kx < KXS; kx++)
                        #pragma unroll
                        for (int j = 0; j <= 12 - kx; j++)
                            fma2(acc[j], zp[j + kx], xx[kx]);
                }
                { // half B: positions 13..21
                    ull zq[9];
                    zq[0] = zrow[13];
                    const ulonglong2* z2 = reinterpret_cast<const ulonglong2*>(zrow + 14);
                    #pragma unroll
                    for (int q = 0; q < 4; q++) {
                        ulonglong2 t = z2[q];
                        zq[1+2*q] = t.x; zq[2+2*q] = t.y;
                    }
                    #pragma unroll
                    for (int kx = 0; kx < KXS; kx++)
                        #pragma unroll
                        for (int j = 13 - kx; j < HO; j++)
                            fma2(acc[j], zq[j + kx - 13], xx[kx]);
                }
            }
        }
        __syncthreads();
    }

    // ---- fold pair lanes, reduce 8 lanes via smem scratch ----
    float* scratch = smem;   // 8*289 floats, fits
    #pragma unroll
    for (int j = 0; j < HO; j++) {
        float lo, hi;
        unpack2(acc[j], lo, hi);
        scratch[lane * OUT_PER_B + i * HO + j] = lo + hi;
    }
    __syncthreads();

    for (int o = tid; o < OUT_PER_B; o += THREADS) {
        float s = 0.f;
        #pragma unroll
        for (int l = 0; l < LANES; l++)
            s += scratch[l * OUT_PER_B + o];
        g_partial[((size_t)split * BATCH + b) * OUT_PER_B + o] = s;
    }
}

// Vectorized reduce: one float4 of outputs per thread.
// N_OUT = 147968 = 36992 * 4 exactly.
__global__ void corr_reduce_kernel(float4* __restrict__ out4)
{
    int idx = blockIdx.x * blockDim.x + threadIdx.x;
    if (idx < N_OUT / 4) {
        const float4* gp4 = reinterpret_cast<const float4*>(g_partial);
        float4 s = gp4[idx];
        #pragma unroll
        for (int sp = 1; sp < SPLITS; sp++) {
            float4 t = gp4[(size_t)sp * (N_OUT / 4) + idx];
            s.x += t.x; s.y += t.y; s.z += t.z; s.w += t.w;
        }
        out4[idx] = s;
    }
}

extern "C" void kernel_launch(void* const* d_in, const int* in_sizes, int n_in,
                              void* d_out, int out_size)
{
    const float* a = (const float*)d_in[0];
    const float* bptr = (const float*)d_in[1];
    const float* x;
    const float* z;
    if (in_sizes[0] == BATCH * CHANNELS * KXS * KXS) { x = a;    z = bptr; }
    else                                             { x = bptr; z = a;   }

    float4* out4 = (float4*)d_out;

    cudaFuncSetAttribute(corr_main_kernel,
                         cudaFuncAttributeMaxDynamicSharedMemorySize, SMEM_BYTES);
    corr_main_kernel<<<BATCH * SPLITS, THREADS, SMEM_BYTES>>>(x, z);
    corr_reduce_kernel<<<(N_OUT / 4 + 255) / 256, 256>>>(out4);
}